// round 12
// baseline (speedup 1.0000x reference)
#include <cuda_runtime.h>
#include <math.h>
#include <stdint.h>

// ---------------------------------------------------------------------------
// GNN_16535624089969: 2-layer GCN (DGL GraphConv norm='both')
//   N=50000, E=800000, dims 256 -> 128 -> 64, fp32.
// R9: - revert R8's tail pipelining (regressor); single agg1/gemm2/agg2.
//     - keep GEMM2 mma bf16 3-split (A pre-split by agg1, W by wconv).
//     - NEW: xconv kernel pre-splits x into bf16 hi/lo once (memory-bound),
//       so GEMM1's mainloop is pure bf16 copies + HMMA (no in-loop cvt).
// ---------------------------------------------------------------------------

#define MAXN 50048
#define MAXE 800000
#define IN_DIM 256
#define HID_DIM 128
#define OUT_DIM 64
#define SCAN_BLK 1024
#define MAX_SCAN_BLOCKS 64
#define SROW 36

__device__ float g_h1[50000 * HID_DIM];              // x@W1 (no norm)
__device__ unsigned short g_xh[50000 * IN_DIM];      // x bf16 hi
__device__ unsigned short g_xl[50000 * IN_DIM];      // x bf16 lo
__device__ unsigned short g_hs2h[50000 * HID_DIM];   // hs2 bf16 hi
__device__ unsigned short g_hs2l[50000 * HID_DIM];   // hs2 bf16 lo
__device__ float g_g2 [50000 * OUT_DIM];             // hs2 @ W2
__device__ unsigned short g_W1th[HID_DIM * IN_DIM];  // W1^T bf16 hi [n][k]
__device__ unsigned short g_W1tl[HID_DIM * IN_DIM];
__device__ unsigned short g_W2th[OUT_DIM * HID_DIM]; // W2^T bf16 hi [n][k]
__device__ unsigned short g_W2tl[OUT_DIM * HID_DIM];
__device__ int   g_csr_src[MAXE];
__device__ int   g_row_ptr[MAXN + 1];
__device__ int   g_cursor[MAXN];
__device__ int   g_outdeg[MAXN];
__device__ int   g_indeg[MAXN];
__device__ float g_ns[MAXN];
__device__ float g_nd[MAXN];
__device__ int   g_block_sums[MAX_SCAN_BLOCKS];

// ---------------------------------------------------------------------------
// helpers
// ---------------------------------------------------------------------------
__device__ __forceinline__ void splitbf(float v, unsigned short& h,
                                        unsigned short& l) {
    unsigned short hh;
    float hf;
    asm("cvt.rn.bf16.f32 %0, %1;" : "=h"(hh) : "f"(v));
    asm("mov.b32 %0, {0, %1};" : "=f"(hf) : "h"(hh));
    float r = v - hf;
    unsigned short ll;
    asm("cvt.rn.bf16.f32 %0, %1;" : "=h"(ll) : "f"(r));
    h = hh; l = ll;
}

__device__ __forceinline__ void mma16816(float* c, const uint32_t* a,
                                         const uint32_t* b) {
    asm volatile(
        "mma.sync.aligned.m16n8k16.row.col.f32.bf16.bf16.f32 "
        "{%0,%1,%2,%3}, {%4,%5,%6,%7}, {%8,%9}, {%0,%1,%2,%3};"
        : "+f"(c[0]), "+f"(c[1]), "+f"(c[2]), "+f"(c[3])
        : "r"(a[0]), "r"(a[1]), "r"(a[2]), "r"(a[3]), "r"(b[0]), "r"(b[1]));
}

// ---------------------------------------------------------------------------
// graph-structure kernels
// ---------------------------------------------------------------------------
__global__ void zero_kernel(int n) {
    int i = blockIdx.x * blockDim.x + threadIdx.x;
    if (i < n) { g_outdeg[i] = 0; g_indeg[i] = 0; g_cursor[i] = 0; }
}

__global__ void deg_kernel(const int* __restrict__ src,
                           const int* __restrict__ dst, int E) {
    int e = blockIdx.x * blockDim.x + threadIdx.x;
    if (e < E) {
        atomicAdd(&g_outdeg[src[e]], 1);
        atomicAdd(&g_indeg[dst[e]], 1);
    }
}

__global__ __launch_bounds__(SCAN_BLK)
void scan1_kernel(int n) {
    int tid = threadIdx.x, i = blockIdx.x * SCAN_BLK + tid;
    int lane = tid & 31, w = tid >> 5;
    if (blockIdx.x == 0 && tid == 0) g_row_ptr[0] = 0;
    int indeg = 0;
    if (i < n) {
        indeg = g_indeg[i];
        g_ns[i] = rsqrtf(fmaxf((float)g_outdeg[i], 1.0f));
        g_nd[i] = rsqrtf(fmaxf((float)indeg, 1.0f));
    }
    int s = indeg;
#pragma unroll
    for (int d = 1; d < 32; d <<= 1) {
        int t = __shfl_up_sync(0xffffffffu, s, d);
        if (lane >= d) s += t;
    }
    __shared__ int wsum[32];
    if (lane == 31) wsum[w] = s;
    __syncthreads();
    if (w == 0) {
        int x = wsum[lane];
#pragma unroll
        for (int d = 1; d < 32; d <<= 1) {
            int t = __shfl_up_sync(0xffffffffu, x, d);
            if (lane >= d) x += t;
        }
        wsum[lane] = x;
    }
    __syncthreads();
    if (w > 0) s += wsum[w - 1];
    if (i < n) g_row_ptr[i + 1] = s;
    if (tid == SCAN_BLK - 1) g_block_sums[blockIdx.x] = s;
}

__global__ __launch_bounds__(SCAN_BLK)
void scan3_kernel(int n) {
    __shared__ int s_off;
    int bid = blockIdx.x;
    if (threadIdx.x < 32) {
        int acc = 0;
        for (int j = threadIdx.x; j < bid; j += 32) acc += g_block_sums[j];
#pragma unroll
        for (int d = 16; d; d >>= 1) acc += __shfl_down_sync(0xffffffffu, acc, d);
        if (threadIdx.x == 0) s_off = acc;
    }
    __syncthreads();
    int i = bid * SCAN_BLK + threadIdx.x;
    if (i < n) g_row_ptr[i + 1] += s_off;
}

__global__ void csr_fill_kernel(const int* __restrict__ src,
                                const int* __restrict__ dst, int E) {
    int e = blockIdx.x * blockDim.x + threadIdx.x;
    if (e < E) {
        int d = dst[e];
        int pos = g_row_ptr[d] + atomicAdd(&g_cursor[d], 1);
        g_csr_src[pos] = src[e];
    }
}

// ---------------------------------------------------------------------------
// conversions (side stream, memory-bound)
// ---------------------------------------------------------------------------
__global__ __launch_bounds__(256)
void xconv_kernel(const float* __restrict__ x, int total4) {
    int i = blockIdx.x * blockDim.x + threadIdx.x;
    if (i >= total4) return;
    float4 v = *(const float4*)&x[(size_t)i * 4];
    unsigned short h[4], l[4];
    splitbf(v.x, h[0], l[0]); splitbf(v.y, h[1], l[1]);
    splitbf(v.z, h[2], l[2]); splitbf(v.w, h[3], l[3]);
    *(uint2*)&g_xh[(size_t)i * 4] = make_uint2(
        (uint32_t)h[0] | ((uint32_t)h[1] << 16),
        (uint32_t)h[2] | ((uint32_t)h[3] << 16));
    *(uint2*)&g_xl[(size_t)i * 4] = make_uint2(
        (uint32_t)l[0] | ((uint32_t)l[1] << 16),
        (uint32_t)l[2] | ((uint32_t)l[3] << 16));
}

__global__ void wconv_kernel(const float* __restrict__ W1,
                             const float* __restrict__ W2) {
    int i = blockIdx.x * blockDim.x + threadIdx.x;
    if (i < HID_DIM * IN_DIM) {
        int nn = i / IN_DIM, k = i % IN_DIM;
        unsigned short h, l;
        splitbf(W1[k * HID_DIM + nn], h, l);
        g_W1th[i] = h; g_W1tl[i] = l;
    }
    if (i < OUT_DIM * HID_DIM) {
        int nn = i / HID_DIM, k = i % HID_DIM;
        unsigned short h, l;
        splitbf(W2[k * OUT_DIM + nn], h, l);
        g_W2th[i] = h; g_W2tl[i] = l;
    }
}

// ---------------------------------------------------------------------------
// GEMM1: C[M,128] = x[M,256] @ W1, mma.sync bf16 3-split.
// A pre-split (g_xh/l), B pre-split (g_W1th/l): mainloop is copies + HMMA.
// ---------------------------------------------------------------------------
__global__ __launch_bounds__(256)
void gemm1_mma_kernel(float* __restrict__ C, int M) {
    __shared__ __align__(16) unsigned short sAh[128 * SROW];
    __shared__ __align__(16) unsigned short sAl[128 * SROW];
    __shared__ __align__(16) unsigned short sBh[128 * SROW];
    __shared__ __align__(16) unsigned short sBl[128 * SROW];

    const int tid = threadIdx.x;
    const int lane = tid & 31, wid = tid >> 5;
    const int g = lane >> 2, t = lane & 3;
    const int warp_m = (wid & 1) * 64;
    const int warp_n = (wid >> 1) * 32;
    const int block_row = blockIdx.x * 128;

    float acc[4][4][4];
#pragma unroll
    for (int i = 0; i < 4; i++)
#pragma unroll
        for (int j = 0; j < 4; j++)
#pragma unroll
            for (int q = 0; q < 4; q++) acc[i][j][q] = 0.0f;

    const int lr = tid >> 1;
    const int lk = tid & 1;

    for (int k0 = 0; k0 < IN_DIM; k0 += 32) {
        // A tile: bf16 copy from pre-split x
        {
            int grow = block_row + lr;
            int sbase = lr * SROW + lk * 16;
            if (grow < M) {
                size_t gbase = (size_t)grow * IN_DIM + k0 + lk * 16;
#pragma unroll
                for (int j = 0; j < 4; j++) {
                    *(uint2*)&sAh[sbase + j * 4] =
                        *(const uint2*)&g_xh[gbase + j * 4];
                    *(uint2*)&sAl[sbase + j * 4] =
                        *(const uint2*)&g_xl[gbase + j * 4];
                }
            } else {
#pragma unroll
                for (int j = 0; j < 4; j++) {
                    *(uint2*)&sAh[sbase + j * 4] = make_uint2(0u, 0u);
                    *(uint2*)&sAl[sbase + j * 4] = make_uint2(0u, 0u);
                }
            }
        }
        // B tile: bf16 copy from pre-split W1t
        {
            int sbase = lr * SROW + lk * 16;
            int gbase = lr * IN_DIM + k0 + lk * 16;
#pragma unroll
            for (int j = 0; j < 4; j++) {
                *(uint2*)&sBh[sbase + j * 4] =
                    *(const uint2*)&g_W1th[gbase + j * 4];
                *(uint2*)&sBl[sbase + j * 4] =
                    *(const uint2*)&g_W1tl[gbase + j * 4];
            }
        }
        __syncthreads();

#pragma unroll
        for (int kk = 0; kk < 32; kk += 16) {
            uint32_t ah[4][4], al[4][4];
#pragma unroll
            for (int mt = 0; mt < 4; mt++) {
                int row = warp_m + mt * 16 + g;
                int b0 = row * SROW + kk + 2 * t;
                ah[mt][0] = *(const uint32_t*)&sAh[b0];
                ah[mt][1] = *(const uint32_t*)&sAh[b0 + 8 * SROW];
                ah[mt][2] = *(const uint32_t*)&sAh[b0 + 8];
                ah[mt][3] = *(const uint32_t*)&sAh[b0 + 8 * SROW + 8];
                al[mt][0] = *(const uint32_t*)&sAl[b0];
                al[mt][1] = *(const uint32_t*)&sAl[b0 + 8 * SROW];
                al[mt][2] = *(const uint32_t*)&sAl[b0 + 8];
                al[mt][3] = *(const uint32_t*)&sAl[b0 + 8 * SROW + 8];
            }
            uint32_t bh[4][2], bl[4][2];
#pragma unroll
            for (int nt = 0; nt < 4; nt++) {
                int nr = warp_n + nt * 8 + g;
                int b0 = nr * SROW + kk + 2 * t;
                bh[nt][0] = *(const uint32_t*)&sBh[b0];
                bh[nt][1] = *(const uint32_t*)&sBh[b0 + 8];
                bl[nt][0] = *(const uint32_t*)&sBl[b0];
                bl[nt][1] = *(const uint32_t*)&sBl[b0 + 8];
            }
#pragma unroll
            for (int mt = 0; mt < 4; mt++)
#pragma unroll
                for (int nt = 0; nt < 4; nt++) {
                    mma16816(acc[mt][nt], ah[mt], bh[nt]);
                    mma16816(acc[mt][nt], al[mt], bh[nt]);
                    mma16816(acc[mt][nt], ah[mt], bl[nt]);
                }
        }
        __syncthreads();
    }

#pragma unroll
    for (int mt = 0; mt < 4; mt++) {
        int row = block_row + warp_m + mt * 16 + g;
#pragma unroll
        for (int nt = 0; nt < 4; nt++) {
            int col = warp_n + nt * 8 + 2 * t;
            if (row < M)
                *(float2*)&C[(size_t)row * HID_DIM + col] =
                    make_float2(acc[mt][nt][0], acc[mt][nt][1]);
            if (row + 8 < M)
                *(float2*)&C[(size_t)(row + 8) * HID_DIM + col] =
                    make_float2(acc[mt][nt][2], acc[mt][nt][3]);
        }
    }
}

// ---------------------------------------------------------------------------
// GEMM2: g2[M,64] = hs2[M,128] @ W2, mma.sync bf16 3-split.
// A pre-split by agg1 (g_hs2h/l), B pre-split (g_W2th/l).
// ---------------------------------------------------------------------------
__global__ __launch_bounds__(256)
void gemm2_mma_kernel(float* __restrict__ C, int M) {
    __shared__ __align__(16) unsigned short sAh[128 * SROW];
    __shared__ __align__(16) unsigned short sAl[128 * SROW];
    __shared__ __align__(16) unsigned short sBh[64 * SROW];
    __shared__ __align__(16) unsigned short sBl[64 * SROW];

    const int tid = threadIdx.x;
    const int lane = tid & 31, wid = tid >> 5;
    const int g = lane >> 2, t = lane & 3;
    const int warp_m = (wid & 1) * 64;
    const int warp_n = (wid >> 1) * 16;
    const int block_row = blockIdx.x * 128;

    float acc[4][2][4];
#pragma unroll
    for (int i = 0; i < 4; i++)
#pragma unroll
        for (int j = 0; j < 2; j++)
#pragma unroll
            for (int q = 0; q < 4; q++) acc[i][j][q] = 0.0f;

    const int lr = tid >> 1;
    const int lk = tid & 1;
    const int br = tid >> 2;
    const int bq = tid & 3;

    for (int k0 = 0; k0 < HID_DIM; k0 += 32) {
        {
            int grow = block_row + lr;
            int sbase = lr * SROW + lk * 16;
            if (grow < M) {
                size_t gbase = (size_t)grow * HID_DIM + k0 + lk * 16;
#pragma unroll
                for (int j = 0; j < 4; j++) {
                    *(uint2*)&sAh[sbase + j * 4] =
                        *(const uint2*)&g_hs2h[gbase + j * 4];
                    *(uint2*)&sAl[sbase + j * 4] =
                        *(const uint2*)&g_hs2l[gbase + j * 4];
                }
            } else {
#pragma unroll
                for (int j = 0; j < 4; j++) {
                    *(uint2*)&sAh[sbase + j * 4] = make_uint2(0u, 0u);
                    *(uint2*)&sAl[sbase + j * 4] = make_uint2(0u, 0u);
                }
            }
        }
        {
            int sbase = br * SROW + bq * 8;
            int gbase = br * HID_DIM + k0 + bq * 8;
#pragma unroll
            for (int j = 0; j < 2; j++) {
                *(uint2*)&sBh[sbase + j * 4] =
                    *(const uint2*)&g_W2th[gbase + j * 4];
                *(uint2*)&sBl[sbase + j * 4] =
                    *(const uint2*)&g_W2tl[gbase + j * 4];
            }
        }
        __syncthreads();

#pragma unroll
        for (int kk = 0; kk < 32; kk += 16) {
            uint32_t ah[4][4], al[4][4];
#pragma unroll
            for (int mt = 0; mt < 4; mt++) {
                int row = warp_m + mt * 16 + g;
                int b0 = row * SROW + kk + 2 * t;
                ah[mt][0] = *(const uint32_t*)&sAh[b0];
                ah[mt][1] = *(const uint32_t*)&sAh[b0 + 8 * SROW];
                ah[mt][2] = *(const uint32_t*)&sAh[b0 + 8];
                ah[mt][3] = *(const uint32_t*)&sAh[b0 + 8 * SROW + 8];
                al[mt][0] = *(const uint32_t*)&sAl[b0];
                al[mt][1] = *(const uint32_t*)&sAl[b0 + 8 * SROW];
                al[mt][2] = *(const uint32_t*)&sAl[b0 + 8];
                al[mt][3] = *(const uint32_t*)&sAl[b0 + 8 * SROW + 8];
            }
            uint32_t bh[2][2], bl[2][2];
#pragma unroll
            for (int nt = 0; nt < 2; nt++) {
                int nr = warp_n + nt * 8 + g;
                int b0 = nr * SROW + kk + 2 * t;
                bh[nt][0] = *(const uint32_t*)&sBh[b0];
                bh[nt][1] = *(const uint32_t*)&sBh[b0 + 8];
                bl[nt][0] = *(const uint32_t*)&sBl[b0];
                bl[nt][1] = *(const uint32_t*)&sBl[b0 + 8];
            }
#pragma unroll
            for (int mt = 0; mt < 4; mt++)
#pragma unroll
                for (int nt = 0; nt < 2; nt++) {
                    mma16816(acc[mt][nt], ah[mt], bh[nt]);
                    mma16816(acc[mt][nt], al[mt], bh[nt]);
                    mma16816(acc[mt][nt], ah[mt], bl[nt]);
                }
        }
        __syncthreads();
    }

#pragma unroll
    for (int mt = 0; mt < 4; mt++) {
        int row = block_row + warp_m + mt * 16 + g;
#pragma unroll
        for (int nt = 0; nt < 2; nt++) {
            int col = warp_n + nt * 8 + 2 * t;
            if (row < M)
                *(float2*)&C[(size_t)row * OUT_DIM + col] =
                    make_float2(acc[mt][nt][0], acc[mt][nt][1]);
            if (row + 8 < M)
                *(float2*)&C[(size_t)(row + 8) * OUT_DIM + col] =
                    make_float2(acc[mt][nt][2], acc[mt][nt][3]);
        }
    }
}

// ---------------------------------------------------------------------------
// Layer-1 aggregation: warp per node; emits hs2 as bf16 hi/lo.
// ---------------------------------------------------------------------------
__global__ __launch_bounds__(256)
void agg1_kernel(const float* __restrict__ b1, int n) {
    int node = blockIdx.x * (blockDim.x >> 5) + (threadIdx.x >> 5);
    if (node >= n) return;
    int lane = threadIdx.x & 31;
    int s = g_row_ptr[node], e = g_row_ptr[node + 1];
    float4 acc = make_float4(0.f, 0.f, 0.f, 0.f);
#pragma unroll 4
    for (int j = s; j < e; j++) {
        int u = g_csr_src[j];
        float nsu = __ldg(&g_ns[u]);
        float4 v = *(const float4*)&g_h1[(size_t)u * HID_DIM + lane * 4];
        acc.x = fmaf(v.x, nsu, acc.x);
        acc.y = fmaf(v.y, nsu, acc.y);
        acc.z = fmaf(v.z, nsu, acc.z);
        acc.w = fmaf(v.w, nsu, acc.w);
    }
    float nd = g_nd[node], ns = g_ns[node];
    float4 bb = *(const float4*)&b1[lane * 4];
    float o[4];
    o[0] = fmaxf(fmaf(acc.x, nd, bb.x), 0.f) * ns;
    o[1] = fmaxf(fmaf(acc.y, nd, bb.y), 0.f) * ns;
    o[2] = fmaxf(fmaf(acc.z, nd, bb.z), 0.f) * ns;
    o[3] = fmaxf(fmaf(acc.w, nd, bb.w), 0.f) * ns;
    unsigned short h[4], l[4];
#pragma unroll
    for (int q = 0; q < 4; q++) splitbf(o[q], h[q], l[q]);
    size_t base = (size_t)node * HID_DIM + lane * 4;
    *(uint2*)&g_hs2h[base] = make_uint2(
        (uint32_t)h[0] | ((uint32_t)h[1] << 16),
        (uint32_t)h[2] | ((uint32_t)h[3] << 16));
    *(uint2*)&g_hs2l[base] = make_uint2(
        (uint32_t)l[0] | ((uint32_t)l[1] << 16),
        (uint32_t)l[2] | ((uint32_t)l[3] << 16));
}

// ---------------------------------------------------------------------------
// Layer-2 aggregation
// ---------------------------------------------------------------------------
__global__ __launch_bounds__(256)
void agg2_kernel(const float* __restrict__ b2, float* __restrict__ out, int n) {
    int node = blockIdx.x * (blockDim.x >> 5) + (threadIdx.x >> 5);
    if (node >= n) return;
    int lane = threadIdx.x & 31;
    int s = g_row_ptr[node], e = g_row_ptr[node + 1];
    float2 acc = make_float2(0.f, 0.f);
#pragma unroll 4
    for (int j = s; j < e; j++) {
        int u = g_csr_src[j];
        float2 v = *(const float2*)&g_g2[(size_t)u * OUT_DIM + lane * 2];
        acc.x += v.x; acc.y += v.y;
    }
    float nd = g_nd[node];
    float2 bb = *(const float2*)&b2[lane * 2];
    float2 o;
    o.x = fmaf(acc.x, nd, bb.x);
    o.y = fmaf(acc.y, nd, bb.y);
    *(float2*)&out[(size_t)node * OUT_DIM + lane * 2] = o;
}

// ---------------------------------------------------------------------------
extern "C" void kernel_launch(void* const* d_in, const int* in_sizes, int n_in,
                              void* d_out, int out_size) {
    const float* x   = (const float*)d_in[0];
    const float* W1  = (const float*)d_in[1];
    const float* b1  = (const float*)d_in[2];
    const float* W2  = (const float*)d_in[3];
    const float* b2  = (const float*)d_in[4];
    const int*   src = (const int*)d_in[5];
    const int*   dst = (const int*)d_in[6];
    float* out = (float*)d_out;

    const int n = in_sizes[0] / IN_DIM;      // 50000
    const int E = in_sizes[5];               // 800000

    float *p_h1, *p_g2;
    cudaGetSymbolAddress((void**)&p_h1, g_h1);
    cudaGetSymbolAddress((void**)&p_g2, g_g2);

    const int nscan = (n + SCAN_BLK - 1) / SCAN_BLK;

    cudaStream_t s2;
    cudaStreamCreate(&s2);
    cudaEvent_t e_fork, e_join;
    cudaEventCreateWithFlags(&e_fork, cudaEventDisableTiming);
    cudaEventCreateWithFlags(&e_join, cudaEventDisableTiming);

    cudaEventRecord(e_fork, 0);
    cudaStreamWaitEvent(s2, e_fork, 0);

    // side stream: x split -> W split -> lean GEMM1 (independent of structure)
    const int total4 = n * IN_DIM / 4;
    xconv_kernel<<<(total4 + 255) / 256, 256, 0, s2>>>(x, total4);
    wconv_kernel<<<(HID_DIM * IN_DIM + 255) / 256, 256, 0, s2>>>(W1, W2);
    gemm1_mma_kernel<<<(n + 127) / 128, 256, 0, s2>>>(p_h1, n);
    cudaEventRecord(e_join, s2);

    // main stream: graph structure
    zero_kernel<<<(n + 255) / 256, 256>>>(n);
    deg_kernel<<<(E + 255) / 256, 256>>>(src, dst, E);
    scan1_kernel<<<nscan, SCAN_BLK>>>(n);
    scan3_kernel<<<nscan, SCAN_BLK>>>(n);
    csr_fill_kernel<<<(E + 255) / 256, 256>>>(src, dst, E);

    cudaStreamWaitEvent(0, e_join, 0);

    // serial tail (no half-split pipelining — R8 showed it regresses)
    agg1_kernel<<<(n + 7) / 8, 256>>>(b1, n);
    gemm2_mma_kernel<<<(n + 127) / 128, 256>>>(p_g2, n);
    agg2_kernel<<<(n + 7) / 8, 256>>>(b2, out, n);
}

// round 14
// speedup vs baseline: 1.2475x; 1.2475x over previous
#include <cuda_runtime.h>
#include <math.h>
#include <stdint.h>

// ---------------------------------------------------------------------------
// GNN_16535624089969: 2-layer GCN (DGL GraphConv norm='both')
//   N=50000, E=800000, dims 256 -> 128 -> 64, fp32.
// R12: exact revert to the 143.0us configuration (R7) with ONE change:
//      GEMM2 f32x2 -> self-contained mma.sync bf16 3-split (A split in-kernel
//      from fp32 hs2, B split in-kernel from fp32 W2). No new kernels, no
//      dependency/scheduling changes (R8/R9 proved those regress).
// ---------------------------------------------------------------------------

#define MAXN 50048
#define MAXE 800000
#define IN_DIM 256
#define HID_DIM 128
#define OUT_DIM 64
#define SCAN_BLK 1024
#define MAX_SCAN_BLOCKS 64
#define SROW 36

__device__ float g_h1[50000 * HID_DIM];    // x@W1 (no norm)
__device__ float g_hs2[50000 * HID_DIM];   // relu(agg1*nd+b1) * norm_src
__device__ float g_g2 [50000 * OUT_DIM];   // hs2 @ W2
__device__ int   g_csr_src[MAXE];
__device__ int   g_row_ptr[MAXN + 1];
__device__ int   g_cursor[MAXN];
__device__ int   g_outdeg[MAXN];
__device__ int   g_indeg[MAXN];
__device__ float g_ns[MAXN];
__device__ float g_nd[MAXN];
__device__ int   g_block_sums[MAX_SCAN_BLOCKS];

// ---------------------------------------------------------------------------
// helpers
// ---------------------------------------------------------------------------
__device__ __forceinline__ void splitbf(float v, unsigned short& h,
                                        unsigned short& l) {
    unsigned short hh;
    float hf;
    asm("cvt.rn.bf16.f32 %0, %1;" : "=h"(hh) : "f"(v));
    asm("mov.b32 %0, {0, %1};" : "=f"(hf) : "h"(hh));
    float r = v - hf;
    unsigned short ll;
    asm("cvt.rn.bf16.f32 %0, %1;" : "=h"(ll) : "f"(r));
    h = hh; l = ll;
}

__device__ __forceinline__ void mma16816(float* c, const uint32_t* a,
                                         const uint32_t* b) {
    asm volatile(
        "mma.sync.aligned.m16n8k16.row.col.f32.bf16.bf16.f32 "
        "{%0,%1,%2,%3}, {%4,%5,%6,%7}, {%8,%9}, {%0,%1,%2,%3};"
        : "+f"(c[0]), "+f"(c[1]), "+f"(c[2]), "+f"(c[3])
        : "r"(a[0]), "r"(a[1]), "r"(a[2]), "r"(a[3]), "r"(b[0]), "r"(b[1]));
}

// ---------------------------------------------------------------------------
// graph-structure kernels
// ---------------------------------------------------------------------------
__global__ void zero_kernel(int n) {
    int i = blockIdx.x * blockDim.x + threadIdx.x;
    if (i < n) { g_outdeg[i] = 0; g_indeg[i] = 0; g_cursor[i] = 0; }
}

__global__ void deg_kernel(const int* __restrict__ src,
                           const int* __restrict__ dst, int E) {
    int e = blockIdx.x * blockDim.x + threadIdx.x;
    if (e < E) {
        atomicAdd(&g_outdeg[src[e]], 1);
        atomicAdd(&g_indeg[dst[e]], 1);
    }
}

__global__ __launch_bounds__(SCAN_BLK)
void scan1_kernel(int n) {
    int tid = threadIdx.x, i = blockIdx.x * SCAN_BLK + tid;
    int lane = tid & 31, w = tid >> 5;
    if (blockIdx.x == 0 && tid == 0) g_row_ptr[0] = 0;
    int indeg = 0;
    if (i < n) {
        indeg = g_indeg[i];
        g_ns[i] = rsqrtf(fmaxf((float)g_outdeg[i], 1.0f));
        g_nd[i] = rsqrtf(fmaxf((float)indeg, 1.0f));
    }
    int s = indeg;
#pragma unroll
    for (int d = 1; d < 32; d <<= 1) {
        int t = __shfl_up_sync(0xffffffffu, s, d);
        if (lane >= d) s += t;
    }
    __shared__ int wsum[32];
    if (lane == 31) wsum[w] = s;
    __syncthreads();
    if (w == 0) {
        int x = wsum[lane];
#pragma unroll
        for (int d = 1; d < 32; d <<= 1) {
            int t = __shfl_up_sync(0xffffffffu, x, d);
            if (lane >= d) x += t;
        }
        wsum[lane] = x;
    }
    __syncthreads();
    if (w > 0) s += wsum[w - 1];
    if (i < n) g_row_ptr[i + 1] = s;
    if (tid == SCAN_BLK - 1) g_block_sums[blockIdx.x] = s;
}

__global__ __launch_bounds__(SCAN_BLK)
void scan3_kernel(int n) {
    __shared__ int s_off;
    int bid = blockIdx.x;
    if (threadIdx.x < 32) {
        int acc = 0;
        for (int j = threadIdx.x; j < bid; j += 32) acc += g_block_sums[j];
#pragma unroll
        for (int d = 16; d; d >>= 1) acc += __shfl_down_sync(0xffffffffu, acc, d);
        if (threadIdx.x == 0) s_off = acc;
    }
    __syncthreads();
    int i = bid * SCAN_BLK + threadIdx.x;
    if (i < n) g_row_ptr[i + 1] += s_off;
}

__global__ void csr_fill_kernel(const int* __restrict__ src,
                                const int* __restrict__ dst, int E) {
    int e = blockIdx.x * blockDim.x + threadIdx.x;
    if (e < E) {
        int d = dst[e];
        int pos = g_row_ptr[d] + atomicAdd(&g_cursor[d], 1);
        g_csr_src[pos] = src[e];
    }
}

// ---------------------------------------------------------------------------
// GEMM1 via mma.sync bf16 3-split: C[M,128] = A[M,256] @ W[256,128]
// (identical to the 143.0us version)
// ---------------------------------------------------------------------------
__global__ __launch_bounds__(256)
void gemm1_mma_kernel(const float* __restrict__ A, const float* __restrict__ W,
                      float* __restrict__ C, int M) {
    __shared__ __align__(16) unsigned short sAh[128 * SROW];
    __shared__ __align__(16) unsigned short sAl[128 * SROW];
    __shared__ __align__(16) unsigned short sBh[128 * SROW];
    __shared__ __align__(16) unsigned short sBl[128 * SROW];

    const int tid = threadIdx.x;
    const int lane = tid & 31, wid = tid >> 5;
    const int g = lane >> 2, t = lane & 3;
    const int warp_m = (wid & 1) * 64;
    const int warp_n = (wid >> 1) * 32;
    const int block_row = blockIdx.x * 128;

    float acc[4][4][4];
#pragma unroll
    for (int i = 0; i < 4; i++)
#pragma unroll
        for (int j = 0; j < 4; j++)
#pragma unroll
            for (int q = 0; q < 4; q++) acc[i][j][q] = 0.0f;

    const int lr = tid >> 1;
    const int lk = tid & 1;

    for (int k0 = 0; k0 < IN_DIM; k0 += 32) {
        // A tile: fp32 -> bf16 hi/lo
        {
            int grow = block_row + lr;
            float v[16];
            if (grow < M) {
                const float4* ap =
                    (const float4*)&A[(size_t)grow * IN_DIM + k0 + lk * 16];
#pragma unroll
                for (int j = 0; j < 4; j++) {
                    float4 f = ap[j];
                    v[j * 4 + 0] = f.x; v[j * 4 + 1] = f.y;
                    v[j * 4 + 2] = f.z; v[j * 4 + 3] = f.w;
                }
            } else {
#pragma unroll
                for (int j = 0; j < 16; j++) v[j] = 0.0f;
            }
            unsigned short h[16], l[16];
#pragma unroll
            for (int j = 0; j < 16; j++) splitbf(v[j], h[j], l[j]);
            int base = lr * SROW + lk * 16;
#pragma unroll
            for (int j = 0; j < 4; j++) {
                *(uint2*)&sAh[base + j * 4] = make_uint2(
                    (uint32_t)h[j*4+0] | ((uint32_t)h[j*4+1] << 16),
                    (uint32_t)h[j*4+2] | ((uint32_t)h[j*4+3] << 16));
                *(uint2*)&sAl[base + j * 4] = make_uint2(
                    (uint32_t)l[j*4+0] | ((uint32_t)l[j*4+1] << 16),
                    (uint32_t)l[j*4+2] | ((uint32_t)l[j*4+3] << 16));
            }
        }
        // B tile: W rows k0..k0+31, cols 0..127 -> sB[n][k]
        {
            int n = lr;
            const float* wp = &W[(size_t)(k0 + lk * 16) * HID_DIM + n];
            unsigned short h[16], l[16];
#pragma unroll
            for (int j = 0; j < 16; j++)
                splitbf(wp[j * HID_DIM], h[j], l[j]);
            int base = n * SROW + lk * 16;
#pragma unroll
            for (int j = 0; j < 4; j++) {
                *(uint2*)&sBh[base + j * 4] = make_uint2(
                    (uint32_t)h[j*4+0] | ((uint32_t)h[j*4+1] << 16),
                    (uint32_t)h[j*4+2] | ((uint32_t)h[j*4+3] << 16));
                *(uint2*)&sBl[base + j * 4] = make_uint2(
                    (uint32_t)l[j*4+0] | ((uint32_t)l[j*4+1] << 16),
                    (uint32_t)l[j*4+2] | ((uint32_t)l[j*4+3] << 16));
            }
        }
        __syncthreads();

#pragma unroll
        for (int kk = 0; kk < 32; kk += 16) {
            uint32_t ah[4][4], al[4][4];
#pragma unroll
            for (int mt = 0; mt < 4; mt++) {
                int row = warp_m + mt * 16 + g;
                int b0 = row * SROW + kk + 2 * t;
                ah[mt][0] = *(const uint32_t*)&sAh[b0];
                ah[mt][1] = *(const uint32_t*)&sAh[b0 + 8 * SROW];
                ah[mt][2] = *(const uint32_t*)&sAh[b0 + 8];
                ah[mt][3] = *(const uint32_t*)&sAh[b0 + 8 * SROW + 8];
                al[mt][0] = *(const uint32_t*)&sAl[b0];
                al[mt][1] = *(const uint32_t*)&sAl[b0 + 8 * SROW];
                al[mt][2] = *(const uint32_t*)&sAl[b0 + 8];
                al[mt][3] = *(const uint32_t*)&sAl[b0 + 8 * SROW + 8];
            }
            uint32_t bh[4][2], bl[4][2];
#pragma unroll
            for (int nt = 0; nt < 4; nt++) {
                int nr = warp_n + nt * 8 + g;
                int b0 = nr * SROW + kk + 2 * t;
                bh[nt][0] = *(const uint32_t*)&sBh[b0];
                bh[nt][1] = *(const uint32_t*)&sBh[b0 + 8];
                bl[nt][0] = *(const uint32_t*)&sBl[b0];
                bl[nt][1] = *(const uint32_t*)&sBl[b0 + 8];
            }
#pragma unroll
            for (int mt = 0; mt < 4; mt++)
#pragma unroll
                for (int nt = 0; nt < 4; nt++) {
                    mma16816(acc[mt][nt], ah[mt], bh[nt]);
                    mma16816(acc[mt][nt], al[mt], bh[nt]);
                    mma16816(acc[mt][nt], ah[mt], bl[nt]);
                }
        }
        __syncthreads();
    }

#pragma unroll
    for (int mt = 0; mt < 4; mt++) {
        int row = block_row + warp_m + mt * 16 + g;
#pragma unroll
        for (int nt = 0; nt < 4; nt++) {
            int col = warp_n + nt * 8 + 2 * t;
            if (row < M)
                *(float2*)&C[(size_t)row * HID_DIM + col] =
                    make_float2(acc[mt][nt][0], acc[mt][nt][1]);
            if (row + 8 < M)
                *(float2*)&C[(size_t)(row + 8) * HID_DIM + col] =
                    make_float2(acc[mt][nt][2], acc[mt][nt][3]);
        }
    }
}

// ---------------------------------------------------------------------------
// GEMM2 via mma.sync bf16 3-split: C[M,64] = hs2[M,128] @ W2[128,64].
// Self-contained: A split in-kernel from fp32 hs2, B from fp32 W2 (strided).
// CTA tile 128x64; warp_m {0,64}, warp_n {0,16,32,48}; mt 4, nt 2.
// ---------------------------------------------------------------------------
__global__ __launch_bounds__(256)
void gemm2_mma_kernel(const float* __restrict__ A, const float* __restrict__ W,
                      float* __restrict__ C, int M) {
    __shared__ __align__(16) unsigned short sAh[128 * SROW];
    __shared__ __align__(16) unsigned short sAl[128 * SROW];
    __shared__ __align__(16) unsigned short sBh[64 * SROW];
    __shared__ __align__(16) unsigned short sBl[64 * SROW];

    const int tid = threadIdx.x;
    const int lane = tid & 31, wid = tid >> 5;
    const int g = lane >> 2, t = lane & 3;
    const int warp_m = (wid & 1) * 64;
    const int warp_n = (wid >> 1) * 16;
    const int block_row = blockIdx.x * 128;

    float acc[4][2][4];
#pragma unroll
    for (int i = 0; i < 4; i++)
#pragma unroll
        for (int j = 0; j < 2; j++)
#pragma unroll
            for (int q = 0; q < 4; q++) acc[i][j][q] = 0.0f;

    const int lr = tid >> 1;      // 0..127 (A row)
    const int lk = tid & 1;       // A k half (16 each)
    const int br = tid >> 2;      // 0..63  (B col = n)
    const int bq = tid & 3;       // B k quarter (8 each)

    for (int k0 = 0; k0 < HID_DIM; k0 += 32) {
        // A tile: fp32 hs2 -> bf16 hi/lo
        {
            int grow = block_row + lr;
            float v[16];
            if (grow < M) {
                const float4* ap =
                    (const float4*)&A[(size_t)grow * HID_DIM + k0 + lk * 16];
#pragma unroll
                for (int j = 0; j < 4; j++) {
                    float4 f = ap[j];
                    v[j * 4 + 0] = f.x; v[j * 4 + 1] = f.y;
                    v[j * 4 + 2] = f.z; v[j * 4 + 3] = f.w;
                }
            } else {
#pragma unroll
                for (int j = 0; j < 16; j++) v[j] = 0.0f;
            }
            unsigned short h[16], l[16];
#pragma unroll
            for (int j = 0; j < 16; j++) splitbf(v[j], h[j], l[j]);
            int base = lr * SROW + lk * 16;
#pragma unroll
            for (int j = 0; j < 4; j++) {
                *(uint2*)&sAh[base + j * 4] = make_uint2(
                    (uint32_t)h[j*4+0] | ((uint32_t)h[j*4+1] << 16),
                    (uint32_t)h[j*4+2] | ((uint32_t)h[j*4+3] << 16));
                *(uint2*)&sAl[base + j * 4] = make_uint2(
                    (uint32_t)l[j*4+0] | ((uint32_t)l[j*4+1] << 16),
                    (uint32_t)l[j*4+2] | ((uint32_t)l[j*4+3] << 16));
            }
        }
        // B tile: W2 rows k0+bq*8..+8, col br -> sB[n][k]
        {
            const float* wp = &W[(size_t)(k0 + bq * 8) * OUT_DIM + br];
            unsigned short h[8], l[8];
#pragma unroll
            for (int j = 0; j < 8; j++)
                splitbf(wp[j * OUT_DIM], h[j], l[j]);
            int base = br * SROW + bq * 8;
#pragma unroll
            for (int j = 0; j < 2; j++) {
                *(uint2*)&sBh[base + j * 4] = make_uint2(
                    (uint32_t)h[j*4+0] | ((uint32_t)h[j*4+1] << 16),
                    (uint32_t)h[j*4+2] | ((uint32_t)h[j*4+3] << 16));
                *(uint2*)&sBl[base + j * 4] = make_uint2(
                    (uint32_t)l[j*4+0] | ((uint32_t)l[j*4+1] << 16),
                    (uint32_t)l[j*4+2] | ((uint32_t)l[j*4+3] << 16));
            }
        }
        __syncthreads();

#pragma unroll
        for (int kk = 0; kk < 32; kk += 16) {
            uint32_t ah[4][4], al[4][4];
#pragma unroll
            for (int mt = 0; mt < 4; mt++) {
                int row = warp_m + mt * 16 + g;
                int b0 = row * SROW + kk + 2 * t;
                ah[mt][0] = *(const uint32_t*)&sAh[b0];
                ah[mt][1] = *(const uint32_t*)&sAh[b0 + 8 * SROW];
                ah[mt][2] = *(const uint32_t*)&sAh[b0 + 8];
                ah[mt][3] = *(const uint32_t*)&sAh[b0 + 8 * SROW + 8];
                al[mt][0] = *(const uint32_t*)&sAl[b0];
                al[mt][1] = *(const uint32_t*)&sAl[b0 + 8 * SROW];
                al[mt][2] = *(const uint32_t*)&sAl[b0 + 8];
                al[mt][3] = *(const uint32_t*)&sAl[b0 + 8 * SROW + 8];
            }
            uint32_t bh[2][2], bl[2][2];
#pragma unroll
            for (int nt = 0; nt < 2; nt++) {
                int nr = warp_n + nt * 8 + g;
                int b0 = nr * SROW + kk + 2 * t;
                bh[nt][0] = *(const uint32_t*)&sBh[b0];
                bh[nt][1] = *(const uint32_t*)&sBh[b0 + 8];
                bl[nt][0] = *(const uint32_t*)&sBl[b0];
                bl[nt][1] = *(const uint32_t*)&sBl[b0 + 8];
            }
#pragma unroll
            for (int mt = 0; mt < 4; mt++)
#pragma unroll
                for (int nt = 0; nt < 2; nt++) {
                    mma16816(acc[mt][nt], ah[mt], bh[nt]);
                    mma16816(acc[mt][nt], al[mt], bh[nt]);
                    mma16816(acc[mt][nt], ah[mt], bl[nt]);
                }
        }
        __syncthreads();
    }

#pragma unroll
    for (int mt = 0; mt < 4; mt++) {
        int row = block_row + warp_m + mt * 16 + g;
#pragma unroll
        for (int nt = 0; nt < 2; nt++) {
            int col = warp_n + nt * 8 + 2 * t;
            if (row < M)
                *(float2*)&C[(size_t)row * OUT_DIM + col] =
                    make_float2(acc[mt][nt][0], acc[mt][nt][1]);
            if (row + 8 < M)
                *(float2*)&C[(size_t)(row + 8) * OUT_DIM + col] =
                    make_float2(acc[mt][nt][2], acc[mt][nt][3]);
        }
    }
}

// ---------------------------------------------------------------------------
// Layer-1 aggregation: warp per node; ns[u] applied per-edge.
// ---------------------------------------------------------------------------
__global__ __launch_bounds__(256)
void agg1_kernel(const float* __restrict__ b1, int n) {
    int node = blockIdx.x * (blockDim.x >> 5) + (threadIdx.x >> 5);
    if (node >= n) return;
    int lane = threadIdx.x & 31;
    int s = g_row_ptr[node], e = g_row_ptr[node + 1];
    float4 acc = make_float4(0.f, 0.f, 0.f, 0.f);
#pragma unroll 4
    for (int j = s; j < e; j++) {
        int u = g_csr_src[j];
        float nsu = __ldg(&g_ns[u]);
        float4 v = *(const float4*)&g_h1[(size_t)u * HID_DIM + lane * 4];
        acc.x = fmaf(v.x, nsu, acc.x);
        acc.y = fmaf(v.y, nsu, acc.y);
        acc.z = fmaf(v.z, nsu, acc.z);
        acc.w = fmaf(v.w, nsu, acc.w);
    }
    float nd = g_nd[node], ns = g_ns[node];
    float4 bb = *(const float4*)&b1[lane * 4];
    float4 o;
    o.x = fmaxf(fmaf(acc.x, nd, bb.x), 0.f) * ns;
    o.y = fmaxf(fmaf(acc.y, nd, bb.y), 0.f) * ns;
    o.z = fmaxf(fmaf(acc.z, nd, bb.z), 0.f) * ns;
    o.w = fmaxf(fmaf(acc.w, nd, bb.w), 0.f) * ns;
    *(float4*)&g_hs2[(size_t)node * HID_DIM + lane * 4] = o;
}

// ---------------------------------------------------------------------------
// Layer-2 aggregation
// ---------------------------------------------------------------------------
__global__ __launch_bounds__(256)
void agg2_kernel(const float* __restrict__ b2, float* __restrict__ out, int n) {
    int node = blockIdx.x * (blockDim.x >> 5) + (threadIdx.x >> 5);
    if (node >= n) return;
    int lane = threadIdx.x & 31;
    int s = g_row_ptr[node], e = g_row_ptr[node + 1];
    float2 acc = make_float2(0.f, 0.f);
#pragma unroll 4
    for (int j = s; j < e; j++) {
        int u = g_csr_src[j];
        float2 v = *(const float2*)&g_g2[(size_t)u * OUT_DIM + lane * 2];
        acc.x += v.x; acc.y += v.y;
    }
    float nd = g_nd[node];
    float2 bb = *(const float2*)&b2[lane * 2];
    float2 o;
    o.x = fmaf(acc.x, nd, bb.x);
    o.y = fmaf(acc.y, nd, bb.y);
    *(float2*)&out[(size_t)node * OUT_DIM + lane * 2] = o;
}

// ---------------------------------------------------------------------------
extern "C" void kernel_launch(void* const* d_in, const int* in_sizes, int n_in,
                              void* d_out, int out_size) {
    const float* x   = (const float*)d_in[0];
    const float* W1  = (const float*)d_in[1];
    const float* b1  = (const float*)d_in[2];
    const float* W2  = (const float*)d_in[3];
    const float* b2  = (const float*)d_in[4];
    const int*   src = (const int*)d_in[5];
    const int*   dst = (const int*)d_in[6];
    float* out = (float*)d_out;

    const int n = in_sizes[0] / IN_DIM;      // 50000
    const int E = in_sizes[5];               // 800000

    float *p_h1, *p_hs2, *p_g2;
    cudaGetSymbolAddress((void**)&p_h1,  g_h1);
    cudaGetSymbolAddress((void**)&p_hs2, g_hs2);
    cudaGetSymbolAddress((void**)&p_g2,  g_g2);

    const int nscan = (n + SCAN_BLK - 1) / SCAN_BLK;

    // fork: GEMM1 (depends only on x, W1) concurrent with structure chain.
    cudaStream_t s2;
    cudaStreamCreate(&s2);
    cudaEvent_t e_fork, e_join;
    cudaEventCreateWithFlags(&e_fork, cudaEventDisableTiming);
    cudaEventCreateWithFlags(&e_join, cudaEventDisableTiming);

    cudaEventRecord(e_fork, 0);
    cudaStreamWaitEvent(s2, e_fork, 0);

    gemm1_mma_kernel<<<(n + 127) / 128, 256, 0, s2>>>(x, W1, p_h1, n);
    cudaEventRecord(e_join, s2);

    zero_kernel<<<(n + 255) / 256, 256>>>(n);
    deg_kernel<<<(E + 255) / 256, 256>>>(src, dst, E);
    scan1_kernel<<<nscan, SCAN_BLK>>>(n);
    scan3_kernel<<<nscan, SCAN_BLK>>>(n);
    csr_fill_kernel<<<(E + 255) / 256, 256>>>(src, dst, E);

    cudaStreamWaitEvent(0, e_join, 0);
    agg1_kernel<<<(n + 7) / 8, 256>>>(b1, n);
    gemm2_mma_kernel<<<(n + 127) / 128, 256>>>(p_hs2, W2, p_g2, n);
    agg2_kernel<<<(n + 7) / 8, 256>>>(b2, out, n);
}

// round 15
// speedup vs baseline: 1.2582x; 1.0086x over previous
#include <cuda_runtime.h>
#include <math.h>
#include <stdint.h>

// ---------------------------------------------------------------------------
// GNN_16535624089969: 2-layer GCN (DGL GraphConv norm='both')
//   N=50000, E=800000, dims 256 -> 128 -> 64, fp32.
// R14: from the 139.5us config, two local changes:
//   - GEMM1: double-buffered dynamic smem (73.7KB), ONE sync per k-chunk.
//   - agg1/agg2: edge-loop unroll 4 -> 8 (deeper index-prefetch MLP).
// ---------------------------------------------------------------------------

#define MAXN 50048
#define MAXE 800000
#define IN_DIM 256
#define HID_DIM 128
#define OUT_DIM 64
#define SCAN_BLK 1024
#define MAX_SCAN_BLOCKS 64
#define SROW 36

__device__ float g_h1[50000 * HID_DIM];    // x@W1 (no norm)
__device__ float g_hs2[50000 * HID_DIM];   // relu(agg1*nd+b1) * norm_src
__device__ float g_g2 [50000 * OUT_DIM];   // hs2 @ W2
__device__ int   g_csr_src[MAXE];
__device__ int   g_row_ptr[MAXN + 1];
__device__ int   g_cursor[MAXN];
__device__ int   g_outdeg[MAXN];
__device__ int   g_indeg[MAXN];
__device__ float g_ns[MAXN];
__device__ float g_nd[MAXN];
__device__ int   g_block_sums[MAX_SCAN_BLOCKS];

// ---------------------------------------------------------------------------
// helpers
// ---------------------------------------------------------------------------
__device__ __forceinline__ void splitbf(float v, unsigned short& h,
                                        unsigned short& l) {
    unsigned short hh;
    float hf;
    asm("cvt.rn.bf16.f32 %0, %1;" : "=h"(hh) : "f"(v));
    asm("mov.b32 %0, {0, %1};" : "=f"(hf) : "h"(hh));
    float r = v - hf;
    unsigned short ll;
    asm("cvt.rn.bf16.f32 %0, %1;" : "=h"(ll) : "f"(r));
    h = hh; l = ll;
}

__device__ __forceinline__ void mma16816(float* c, const uint32_t* a,
                                         const uint32_t* b) {
    asm volatile(
        "mma.sync.aligned.m16n8k16.row.col.f32.bf16.bf16.f32 "
        "{%0,%1,%2,%3}, {%4,%5,%6,%7}, {%8,%9}, {%0,%1,%2,%3};"
        : "+f"(c[0]), "+f"(c[1]), "+f"(c[2]), "+f"(c[3])
        : "r"(a[0]), "r"(a[1]), "r"(a[2]), "r"(a[3]), "r"(b[0]), "r"(b[1]));
}

// ---------------------------------------------------------------------------
// graph-structure kernels
// ---------------------------------------------------------------------------
__global__ void zero_kernel(int n) {
    int i = blockIdx.x * blockDim.x + threadIdx.x;
    if (i < n) { g_outdeg[i] = 0; g_indeg[i] = 0; g_cursor[i] = 0; }
}

__global__ void deg_kernel(const int* __restrict__ src,
                           const int* __restrict__ dst, int E) {
    int e = blockIdx.x * blockDim.x + threadIdx.x;
    if (e < E) {
        atomicAdd(&g_outdeg[src[e]], 1);
        atomicAdd(&g_indeg[dst[e]], 1);
    }
}

__global__ __launch_bounds__(SCAN_BLK)
void scan1_kernel(int n) {
    int tid = threadIdx.x, i = blockIdx.x * SCAN_BLK + tid;
    int lane = tid & 31, w = tid >> 5;
    if (blockIdx.x == 0 && tid == 0) g_row_ptr[0] = 0;
    int indeg = 0;
    if (i < n) {
        indeg = g_indeg[i];
        g_ns[i] = rsqrtf(fmaxf((float)g_outdeg[i], 1.0f));
        g_nd[i] = rsqrtf(fmaxf((float)indeg, 1.0f));
    }
    int s = indeg;
#pragma unroll
    for (int d = 1; d < 32; d <<= 1) {
        int t = __shfl_up_sync(0xffffffffu, s, d);
        if (lane >= d) s += t;
    }
    __shared__ int wsum[32];
    if (lane == 31) wsum[w] = s;
    __syncthreads();
    if (w == 0) {
        int x = wsum[lane];
#pragma unroll
        for (int d = 1; d < 32; d <<= 1) {
            int t = __shfl_up_sync(0xffffffffu, x, d);
            if (lane >= d) x += t;
        }
        wsum[lane] = x;
    }
    __syncthreads();
    if (w > 0) s += wsum[w - 1];
    if (i < n) g_row_ptr[i + 1] = s;
    if (tid == SCAN_BLK - 1) g_block_sums[blockIdx.x] = s;
}

__global__ __launch_bounds__(SCAN_BLK)
void scan3_kernel(int n) {
    __shared__ int s_off;
    int bid = blockIdx.x;
    if (threadIdx.x < 32) {
        int acc = 0;
        for (int j = threadIdx.x; j < bid; j += 32) acc += g_block_sums[j];
#pragma unroll
        for (int d = 16; d; d >>= 1) acc += __shfl_down_sync(0xffffffffu, acc, d);
        if (threadIdx.x == 0) s_off = acc;
    }
    __syncthreads();
    int i = bid * SCAN_BLK + threadIdx.x;
    if (i < n) g_row_ptr[i + 1] += s_off;
}

__global__ void csr_fill_kernel(const int* __restrict__ src,
                                const int* __restrict__ dst, int E) {
    int e = blockIdx.x * blockDim.x + threadIdx.x;
    if (e < E) {
        int d = dst[e];
        int pos = g_row_ptr[d] + atomicAdd(&g_cursor[d], 1);
        g_csr_src[pos] = src[e];
    }
}

// ---------------------------------------------------------------------------
// GEMM1 via mma.sync bf16 3-split: C[M,128] = A[M,256] @ W[256,128]
// Double-buffered dynamic smem: layout per buffer [AH|AL|BH|BL], each
// 128*SROW ushorts (9216B); 2 buffers = 73728B. One __syncthreads per chunk.
// ---------------------------------------------------------------------------
#define TILE_ELEMS (128 * SROW)

__global__ __launch_bounds__(256)
void gemm1_mma_kernel(const float* __restrict__ A, const float* __restrict__ W,
                      float* __restrict__ C, int M) {
    extern __shared__ __align__(16) unsigned short dsm[];

    const int tid = threadIdx.x;
    const int lane = tid & 31, wid = tid >> 5;
    const int g = lane >> 2, t = lane & 3;
    const int warp_m = (wid & 1) * 64;
    const int warp_n = (wid >> 1) * 32;
    const int block_row = blockIdx.x * 128;

    float acc[4][4][4];
#pragma unroll
    for (int i = 0; i < 4; i++)
#pragma unroll
        for (int j = 0; j < 4; j++)
#pragma unroll
            for (int q = 0; q < 4; q++) acc[i][j][q] = 0.0f;

    const int lr = tid >> 1;
    const int lk = tid & 1;

    for (int ch = 0; ch < IN_DIM / 32; ch++) {
        const int k0 = ch * 32;
        unsigned short* sAh = dsm + (ch & 1) * 4 * TILE_ELEMS;
        unsigned short* sAl = sAh + TILE_ELEMS;
        unsigned short* sBh = sAl + TILE_ELEMS;
        unsigned short* sBl = sBh + TILE_ELEMS;

        // A tile: fp32 -> bf16 hi/lo
        {
            int grow = block_row + lr;
            float v[16];
            if (grow < M) {
                const float4* ap =
                    (const float4*)&A[(size_t)grow * IN_DIM + k0 + lk * 16];
#pragma unroll
                for (int j = 0; j < 4; j++) {
                    float4 f = ap[j];
                    v[j * 4 + 0] = f.x; v[j * 4 + 1] = f.y;
                    v[j * 4 + 2] = f.z; v[j * 4 + 3] = f.w;
                }
            } else {
#pragma unroll
                for (int j = 0; j < 16; j++) v[j] = 0.0f;
            }
            unsigned short h[16], l[16];
#pragma unroll
            for (int j = 0; j < 16; j++) splitbf(v[j], h[j], l[j]);
            int base = lr * SROW + lk * 16;
#pragma unroll
            for (int j = 0; j < 4; j++) {
                *(uint2*)&sAh[base + j * 4] = make_uint2(
                    (uint32_t)h[j*4+0] | ((uint32_t)h[j*4+1] << 16),
                    (uint32_t)h[j*4+2] | ((uint32_t)h[j*4+3] << 16));
                *(uint2*)&sAl[base + j * 4] = make_uint2(
                    (uint32_t)l[j*4+0] | ((uint32_t)l[j*4+1] << 16),
                    (uint32_t)l[j*4+2] | ((uint32_t)l[j*4+3] << 16));
            }
        }
        // B tile: W rows k0..k0+31, cols 0..127 -> sB[n][k]
        {
            int n = lr;
            const float* wp = &W[(size_t)(k0 + lk * 16) * HID_DIM + n];
            unsigned short h[16], l[16];
#pragma unroll
            for (int j = 0; j < 16; j++)
                splitbf(wp[j * HID_DIM], h[j], l[j]);
            int base = n * SROW + lk * 16;
#pragma unroll
            for (int j = 0; j < 4; j++) {
                *(uint2*)&sBh[base + j * 4] = make_uint2(
                    (uint32_t)h[j*4+0] | ((uint32_t)h[j*4+1] << 16),
                    (uint32_t)h[j*4+2] | ((uint32_t)h[j*4+3] << 16));
                *(uint2*)&sBl[base + j * 4] = make_uint2(
                    (uint32_t)l[j*4+0] | ((uint32_t)l[j*4+1] << 16),
                    (uint32_t)l[j*4+2] | ((uint32_t)l[j*4+3] << 16));
            }
        }
        __syncthreads();   // single barrier per chunk (double-buffered)

#pragma unroll
        for (int kk = 0; kk < 32; kk += 16) {
            uint32_t ah[4][4], al[4][4];
#pragma unroll
            for (int mt = 0; mt < 4; mt++) {
                int row = warp_m + mt * 16 + g;
                int b0 = row * SROW + kk + 2 * t;
                ah[mt][0] = *(const uint32_t*)&sAh[b0];
                ah[mt][1] = *(const uint32_t*)&sAh[b0 + 8 * SROW];
                ah[mt][2] = *(const uint32_t*)&sAh[b0 + 8];
                ah[mt][3] = *(const uint32_t*)&sAh[b0 + 8 * SROW + 8];
                al[mt][0] = *(const uint32_t*)&sAl[b0];
                al[mt][1] = *(const uint32_t*)&sAl[b0 + 8 * SROW];
                al[mt][2] = *(const uint32_t*)&sAl[b0 + 8];
                al[mt][3] = *(const uint32_t*)&sAl[b0 + 8 * SROW + 8];
            }
            uint32_t bh[4][2], bl[4][2];
#pragma unroll
            for (int nt = 0; nt < 4; nt++) {
                int nr = warp_n + nt * 8 + g;
                int b0 = nr * SROW + kk + 2 * t;
                bh[nt][0] = *(const uint32_t*)&sBh[b0];
                bh[nt][1] = *(const uint32_t*)&sBh[b0 + 8];
                bl[nt][0] = *(const uint32_t*)&sBl[b0];
                bl[nt][1] = *(const uint32_t*)&sBl[b0 + 8];
            }
#pragma unroll
            for (int mt = 0; mt < 4; mt++)
#pragma unroll
                for (int nt = 0; nt < 4; nt++) {
                    mma16816(acc[mt][nt], ah[mt], bh[nt]);
                    mma16816(acc[mt][nt], al[mt], bh[nt]);
                    mma16816(acc[mt][nt], ah[mt], bl[nt]);
                }
        }
    }

#pragma unroll
    for (int mt = 0; mt < 4; mt++) {
        int row = block_row + warp_m + mt * 16 + g;
#pragma unroll
        for (int nt = 0; nt < 4; nt++) {
            int col = warp_n + nt * 8 + 2 * t;
            if (row < M)
                *(float2*)&C[(size_t)row * HID_DIM + col] =
                    make_float2(acc[mt][nt][0], acc[mt][nt][1]);
            if (row + 8 < M)
                *(float2*)&C[(size_t)(row + 8) * HID_DIM + col] =
                    make_float2(acc[mt][nt][2], acc[mt][nt][3]);
        }
    }
}

// ---------------------------------------------------------------------------
// GEMM2 via mma.sync bf16 3-split: C[M,64] = hs2[M,128] @ W2[128,64].
// (unchanged from the 139.5us winner)
// ---------------------------------------------------------------------------
__global__ __launch_bounds__(256)
void gemm2_mma_kernel(const float* __restrict__ A, const float* __restrict__ W,
                      float* __restrict__ C, int M) {
    __shared__ __align__(16) unsigned short sAh[128 * SROW];
    __shared__ __align__(16) unsigned short sAl[128 * SROW];
    __shared__ __align__(16) unsigned short sBh[64 * SROW];
    __shared__ __align__(16) unsigned short sBl[64 * SROW];

    const int tid = threadIdx.x;
    const int lane = tid & 31, wid = tid >> 5;
    const int g = lane >> 2, t = lane & 3;
    const int warp_m = (wid & 1) * 64;
    const int warp_n = (wid >> 1) * 16;
    const int block_row = blockIdx.x * 128;

    float acc[4][2][4];
#pragma unroll
    for (int i = 0; i < 4; i++)
#pragma unroll
        for (int j = 0; j < 2; j++)
#pragma unroll
            for (int q = 0; q < 4; q++) acc[i][j][q] = 0.0f;

    const int lr = tid >> 1;
    const int lk = tid & 1;
    const int br = tid >> 2;
    const int bq = tid & 3;

    for (int k0 = 0; k0 < HID_DIM; k0 += 32) {
        {
            int grow = block_row + lr;
            float v[16];
            if (grow < M) {
                const float4* ap =
                    (const float4*)&A[(size_t)grow * HID_DIM + k0 + lk * 16];
#pragma unroll
                for (int j = 0; j < 4; j++) {
                    float4 f = ap[j];
                    v[j * 4 + 0] = f.x; v[j * 4 + 1] = f.y;
                    v[j * 4 + 2] = f.z; v[j * 4 + 3] = f.w;
                }
            } else {
#pragma unroll
                for (int j = 0; j < 16; j++) v[j] = 0.0f;
            }
            unsigned short h[16], l[16];
#pragma unroll
            for (int j = 0; j < 16; j++) splitbf(v[j], h[j], l[j]);
            int base = lr * SROW + lk * 16;
#pragma unroll
            for (int j = 0; j < 4; j++) {
                *(uint2*)&sAh[base + j * 4] = make_uint2(
                    (uint32_t)h[j*4+0] | ((uint32_t)h[j*4+1] << 16),
                    (uint32_t)h[j*4+2] | ((uint32_t)h[j*4+3] << 16));
                *(uint2*)&sAl[base + j * 4] = make_uint2(
                    (uint32_t)l[j*4+0] | ((uint32_t)l[j*4+1] << 16),
                    (uint32_t)l[j*4+2] | ((uint32_t)l[j*4+3] << 16));
            }
        }
        {
            const float* wp = &W[(size_t)(k0 + bq * 8) * OUT_DIM + br];
            unsigned short h[8], l[8];
#pragma unroll
            for (int j = 0; j < 8; j++)
                splitbf(wp[j * OUT_DIM], h[j], l[j]);
            int base = br * SROW + bq * 8;
#pragma unroll
            for (int j = 0; j < 2; j++) {
                *(uint2*)&sBh[base + j * 4] = make_uint2(
                    (uint32_t)h[j*4+0] | ((uint32_t)h[j*4+1] << 16),
                    (uint32_t)h[j*4+2] | ((uint32_t)h[j*4+3] << 16));
                *(uint2*)&sBl[base + j * 4] = make_uint2(
                    (uint32_t)l[j*4+0] | ((uint32_t)l[j*4+1] << 16),
                    (uint32_t)l[j*4+2] | ((uint32_t)l[j*4+3] << 16));
            }
        }
        __syncthreads();

#pragma unroll
        for (int kk = 0; kk < 32; kk += 16) {
            uint32_t ah[4][4], al[4][4];
#pragma unroll
            for (int mt = 0; mt < 4; mt++) {
                int row = warp_m + mt * 16 + g;
                int b0 = row * SROW + kk + 2 * t;
                ah[mt][0] = *(const uint32_t*)&sAh[b0];
                ah[mt][1] = *(const uint32_t*)&sAh[b0 + 8 * SROW];
                ah[mt][2] = *(const uint32_t*)&sAh[b0 + 8];
                ah[mt][3] = *(const uint32_t*)&sAh[b0 + 8 * SROW + 8];
                al[mt][0] = *(const uint32_t*)&sAl[b0];
                al[mt][1] = *(const uint32_t*)&sAl[b0 + 8 * SROW];
                al[mt][2] = *(const uint32_t*)&sAl[b0 + 8];
                al[mt][3] = *(const uint32_t*)&sAl[b0 + 8 * SROW + 8];
            }
            uint32_t bh[2][2], bl[2][2];
#pragma unroll
            for (int nt = 0; nt < 2; nt++) {
                int nr = warp_n + nt * 8 + g;
                int b0 = nr * SROW + kk + 2 * t;
                bh[nt][0] = *(const uint32_t*)&sBh[b0];
                bh[nt][1] = *(const uint32_t*)&sBh[b0 + 8];
                bl[nt][0] = *(const uint32_t*)&sBl[b0];
                bl[nt][1] = *(const uint32_t*)&sBl[b0 + 8];
            }
#pragma unroll
            for (int mt = 0; mt < 4; mt++)
#pragma unroll
                for (int nt = 0; nt < 2; nt++) {
                    mma16816(acc[mt][nt], ah[mt], bh[nt]);
                    mma16816(acc[mt][nt], al[mt], bh[nt]);
                    mma16816(acc[mt][nt], ah[mt], bl[nt]);
                }
        }
        __syncthreads();
    }

#pragma unroll
    for (int mt = 0; mt < 4; mt++) {
        int row = block_row + warp_m + mt * 16 + g;
#pragma unroll
        for (int nt = 0; nt < 2; nt++) {
            int col = warp_n + nt * 8 + 2 * t;
            if (row < M)
                *(float2*)&C[(size_t)row * OUT_DIM + col] =
                    make_float2(acc[mt][nt][0], acc[mt][nt][1]);
            if (row + 8 < M)
                *(float2*)&C[(size_t)(row + 8) * OUT_DIM + col] =
                    make_float2(acc[mt][nt][2], acc[mt][nt][3]);
        }
    }
}

// ---------------------------------------------------------------------------
// Layer-1 aggregation: warp per node; ns[u] applied per-edge. unroll 8.
// ---------------------------------------------------------------------------
__global__ __launch_bounds__(256)
void agg1_kernel(const float* __restrict__ b1, int n) {
    int node = blockIdx.x * (blockDim.x >> 5) + (threadIdx.x >> 5);
    if (node >= n) return;
    int lane = threadIdx.x & 31;
    int s = g_row_ptr[node], e = g_row_ptr[node + 1];
    float4 acc = make_float4(0.f, 0.f, 0.f, 0.f);
#pragma unroll 8
    for (int j = s; j < e; j++) {
        int u = g_csr_src[j];
        float nsu = __ldg(&g_ns[u]);
        float4 v = *(const float4*)&g_h1[(size_t)u * HID_DIM + lane * 4];
        acc.x = fmaf(v.x, nsu, acc.x);
        acc.y = fmaf(v.y, nsu, acc.y);
        acc.z = fmaf(v.z, nsu, acc.z);
        acc.w = fmaf(v.w, nsu, acc.w);
    }
    float nd = g_nd[node], ns = g_ns[node];
    float4 bb = *(const float4*)&b1[lane * 4];
    float4 o;
    o.x = fmaxf(fmaf(acc.x, nd, bb.x), 0.f) * ns;
    o.y = fmaxf(fmaf(acc.y, nd, bb.y), 0.f) * ns;
    o.z = fmaxf(fmaf(acc.z, nd, bb.z), 0.f) * ns;
    o.w = fmaxf(fmaf(acc.w, nd, bb.w), 0.f) * ns;
    *(float4*)&g_hs2[(size_t)node * HID_DIM + lane * 4] = o;
}

// ---------------------------------------------------------------------------
// Layer-2 aggregation. unroll 8.
// ---------------------------------------------------------------------------
__global__ __launch_bounds__(256)
void agg2_kernel(const float* __restrict__ b2, float* __restrict__ out, int n) {
    int node = blockIdx.x * (blockDim.x >> 5) + (threadIdx.x >> 5);
    if (node >= n) return;
    int lane = threadIdx.x & 31;
    int s = g_row_ptr[node], e = g_row_ptr[node + 1];
    float2 acc = make_float2(0.f, 0.f);
#pragma unroll 8
    for (int j = s; j < e; j++) {
        int u = g_csr_src[j];
        float2 v = *(const float2*)&g_g2[(size_t)u * OUT_DIM + lane * 2];
        acc.x += v.x; acc.y += v.y;
    }
    float nd = g_nd[node];
    float2 bb = *(const float2*)&b2[lane * 2];
    float2 o;
    o.x = fmaf(acc.x, nd, bb.x);
    o.y = fmaf(acc.y, nd, bb.y);
    *(float2*)&out[(size_t)node * OUT_DIM + lane * 2] = o;
}

// ---------------------------------------------------------------------------
extern "C" void kernel_launch(void* const* d_in, const int* in_sizes, int n_in,
                              void* d_out, int out_size) {
    const float* x   = (const float*)d_in[0];
    const float* W1  = (const float*)d_in[1];
    const float* b1  = (const float*)d_in[2];
    const float* W2  = (const float*)d_in[3];
    const float* b2  = (const float*)d_in[4];
    const int*   src = (const int*)d_in[5];
    const int*   dst = (const int*)d_in[6];
    float* out = (float*)d_out;

    const int n = in_sizes[0] / IN_DIM;      // 50000
    const int E = in_sizes[5];               // 800000

    float *p_h1, *p_hs2, *p_g2;
    cudaGetSymbolAddress((void**)&p_h1,  g_h1);
    cudaGetSymbolAddress((void**)&p_hs2, g_hs2);
    cudaGetSymbolAddress((void**)&p_g2,  g_g2);

    const int nscan = (n + SCAN_BLK - 1) / SCAN_BLK;
    const int GEMM1_SMEM = 8 * TILE_ELEMS * (int)sizeof(unsigned short); // 73728
    cudaFuncSetAttribute(gemm1_mma_kernel,
                         cudaFuncAttributeMaxDynamicSharedMemorySize,
                         GEMM1_SMEM);

    // fork: GEMM1 (depends only on x, W1) concurrent with structure chain.
    cudaStream_t s2;
    cudaStreamCreate(&s2);
    cudaEvent_t e_fork, e_join;
    cudaEventCreateWithFlags(&e_fork, cudaEventDisableTiming);
    cudaEventCreateWithFlags(&e_join, cudaEventDisableTiming);

    cudaEventRecord(e_fork, 0);
    cudaStreamWaitEvent(s2, e_fork, 0);

    gemm1_mma_kernel<<<(n + 127) / 128, 256, GEMM1_SMEM, s2>>>(x, W1, p_h1, n);
    cudaEventRecord(e_join, s2);

    zero_kernel<<<(n + 255) / 256, 256>>>(n);
    deg_kernel<<<(E + 255) / 256, 256>>>(src, dst, E);
    scan1_kernel<<<nscan, SCAN_BLK>>>(n);
    scan3_kernel<<<nscan, SCAN_BLK>>>(n);
    csr_fill_kernel<<<(E + 255) / 256, 256>>>(src, dst, E);

    cudaStreamWaitEvent(0, e_join, 0);
    agg1_kernel<<<(n + 7) / 8, 256>>>(b1, n);
    gemm2_mma_kernel<<<(n + 127) / 128, 256>>>(p_hs2, W2, p_g2, n);
    agg2_kernel<<<(n + 7) / 8, 256>>>(b2, out, n);
}

// round 17
// speedup vs baseline: 1.2957x; 1.0298x over previous
#include <cuda_runtime.h>
#include <cuda_fp16.h>
#include <math.h>
#include <stdint.h>

// ---------------------------------------------------------------------------
// GNN_16535624089969: 2-layer GCN (DGL GraphConv norm='both')
//   N=50000, E=800000, dims 256 -> 128 -> 64, fp32 in/out.
// R15: from the 138.3us config, ONE conceptual change: the gather tables
//   h1 and g2 are stored as fp16 (written by the GEMM epilogues, read by the
//   agg kernels). Halves agg L2 traffic (410->210MB, 205->103MB). All
//   accumulation stays fp32; expected rel_err ~3e-4 (tolerance 1e-3).
// ---------------------------------------------------------------------------

#define MAXN 50048
#define MAXE 800000
#define IN_DIM 256
#define HID_DIM 128
#define OUT_DIM 64
#define SCAN_BLK 1024
#define MAX_SCAN_BLOCKS 64
#define SROW 36

__device__ unsigned short g_h1h[50000 * HID_DIM];  // x@W1 as fp16
__device__ float g_hs2[50000 * HID_DIM];           // relu(agg1*nd+b1)*ns, fp32
__device__ unsigned short g_g2h[50000 * OUT_DIM];  // hs2@W2 as fp16
__device__ int   g_csr_src[MAXE];
__device__ int   g_row_ptr[MAXN + 1];
__device__ int   g_cursor[MAXN];
__device__ int   g_outdeg[MAXN];
__device__ int   g_indeg[MAXN];
__device__ float g_ns[MAXN];
__device__ float g_nd[MAXN];
__device__ int   g_block_sums[MAX_SCAN_BLOCKS];

// ---------------------------------------------------------------------------
// helpers
// ---------------------------------------------------------------------------
__device__ __forceinline__ void splitbf(float v, unsigned short& h,
                                        unsigned short& l) {
    unsigned short hh;
    float hf;
    asm("cvt.rn.bf16.f32 %0, %1;" : "=h"(hh) : "f"(v));
    asm("mov.b32 %0, {0, %1};" : "=f"(hf) : "h"(hh));
    float r = v - hf;
    unsigned short ll;
    asm("cvt.rn.bf16.f32 %0, %1;" : "=h"(ll) : "f"(r));
    h = hh; l = ll;
}

__device__ __forceinline__ void mma16816(float* c, const uint32_t* a,
                                         const uint32_t* b) {
    asm volatile(
        "mma.sync.aligned.m16n8k16.row.col.f32.bf16.bf16.f32 "
        "{%0,%1,%2,%3}, {%4,%5,%6,%7}, {%8,%9}, {%0,%1,%2,%3};"
        : "+f"(c[0]), "+f"(c[1]), "+f"(c[2]), "+f"(c[3])
        : "r"(a[0]), "r"(a[1]), "r"(a[2]), "r"(a[3]), "r"(b[0]), "r"(b[1]));
}

// ---------------------------------------------------------------------------
// graph-structure kernels (unchanged)
// ---------------------------------------------------------------------------
__global__ void zero_kernel(int n) {
    int i = blockIdx.x * blockDim.x + threadIdx.x;
    if (i < n) { g_outdeg[i] = 0; g_indeg[i] = 0; g_cursor[i] = 0; }
}

__global__ void deg_kernel(const int* __restrict__ src,
                           const int* __restrict__ dst, int E) {
    int e = blockIdx.x * blockDim.x + threadIdx.x;
    if (e < E) {
        atomicAdd(&g_outdeg[src[e]], 1);
        atomicAdd(&g_indeg[dst[e]], 1);
    }
}

__global__ __launch_bounds__(SCAN_BLK)
void scan1_kernel(int n) {
    int tid = threadIdx.x, i = blockIdx.x * SCAN_BLK + tid;
    int lane = tid & 31, w = tid >> 5;
    if (blockIdx.x == 0 && tid == 0) g_row_ptr[0] = 0;
    int indeg = 0;
    if (i < n) {
        indeg = g_indeg[i];
        g_ns[i] = rsqrtf(fmaxf((float)g_outdeg[i], 1.0f));
        g_nd[i] = rsqrtf(fmaxf((float)indeg, 1.0f));
    }
    int s = indeg;
#pragma unroll
    for (int d = 1; d < 32; d <<= 1) {
        int t = __shfl_up_sync(0xffffffffu, s, d);
        if (lane >= d) s += t;
    }
    __shared__ int wsum[32];
    if (lane == 31) wsum[w] = s;
    __syncthreads();
    if (w == 0) {
        int x = wsum[lane];
#pragma unroll
        for (int d = 1; d < 32; d <<= 1) {
            int t = __shfl_up_sync(0xffffffffu, x, d);
            if (lane >= d) x += t;
        }
        wsum[lane] = x;
    }
    __syncthreads();
    if (w > 0) s += wsum[w - 1];
    if (i < n) g_row_ptr[i + 1] = s;
    if (tid == SCAN_BLK - 1) g_block_sums[blockIdx.x] = s;
}

__global__ __launch_bounds__(SCAN_BLK)
void scan3_kernel(int n) {
    __shared__ int s_off;
    int bid = blockIdx.x;
    if (threadIdx.x < 32) {
        int acc = 0;
        for (int j = threadIdx.x; j < bid; j += 32) acc += g_block_sums[j];
#pragma unroll
        for (int d = 16; d; d >>= 1) acc += __shfl_down_sync(0xffffffffu, acc, d);
        if (threadIdx.x == 0) s_off = acc;
    }
    __syncthreads();
    int i = bid * SCAN_BLK + threadIdx.x;
    if (i < n) g_row_ptr[i + 1] += s_off;
}

__global__ void csr_fill_kernel(const int* __restrict__ src,
                                const int* __restrict__ dst, int E) {
    int e = blockIdx.x * blockDim.x + threadIdx.x;
    if (e < E) {
        int d = dst[e];
        int pos = g_row_ptr[d] + atomicAdd(&g_cursor[d], 1);
        g_csr_src[pos] = src[e];
    }
}

// ---------------------------------------------------------------------------
// GEMM1 via mma.sync bf16 3-split: h1 = x[M,256] @ W1[256,128], fp16 out.
// Double-buffered dynamic smem, one __syncthreads per k-chunk.
// ---------------------------------------------------------------------------
#define TILE_ELEMS (128 * SROW)

__global__ __launch_bounds__(256)
void gemm1_mma_kernel(const float* __restrict__ A, const float* __restrict__ W,
                      unsigned short* __restrict__ H, int M) {
    extern __shared__ __align__(16) unsigned short dsm[];

    const int tid = threadIdx.x;
    const int lane = tid & 31, wid = tid >> 5;
    const int g = lane >> 2, t = lane & 3;
    const int warp_m = (wid & 1) * 64;
    const int warp_n = (wid >> 1) * 32;
    const int block_row = blockIdx.x * 128;

    float acc[4][4][4];
#pragma unroll
    for (int i = 0; i < 4; i++)
#pragma unroll
        for (int j = 0; j < 4; j++)
#pragma unroll
            for (int q = 0; q < 4; q++) acc[i][j][q] = 0.0f;

    const int lr = tid >> 1;
    const int lk = tid & 1;

    for (int ch = 0; ch < IN_DIM / 32; ch++) {
        const int k0 = ch * 32;
        unsigned short* sAh = dsm + (ch & 1) * 4 * TILE_ELEMS;
        unsigned short* sAl = sAh + TILE_ELEMS;
        unsigned short* sBh = sAl + TILE_ELEMS;
        unsigned short* sBl = sBh + TILE_ELEMS;

        // A tile: fp32 -> bf16 hi/lo
        {
            int grow = block_row + lr;
            float v[16];
            if (grow < M) {
                const float4* ap =
                    (const float4*)&A[(size_t)grow * IN_DIM + k0 + lk * 16];
#pragma unroll
                for (int j = 0; j < 4; j++) {
                    float4 f = ap[j];
                    v[j * 4 + 0] = f.x; v[j * 4 + 1] = f.y;
                    v[j * 4 + 2] = f.z; v[j * 4 + 3] = f.w;
                }
            } else {
#pragma unroll
                for (int j = 0; j < 16; j++) v[j] = 0.0f;
            }
            unsigned short h[16], l[16];
#pragma unroll
            for (int j = 0; j < 16; j++) splitbf(v[j], h[j], l[j]);
            int base = lr * SROW + lk * 16;
#pragma unroll
            for (int j = 0; j < 4; j++) {
                *(uint2*)&sAh[base + j * 4] = make_uint2(
                    (uint32_t)h[j*4+0] | ((uint32_t)h[j*4+1] << 16),
                    (uint32_t)h[j*4+2] | ((uint32_t)h[j*4+3] << 16));
                *(uint2*)&sAl[base + j * 4] = make_uint2(
                    (uint32_t)l[j*4+0] | ((uint32_t)l[j*4+1] << 16),
                    (uint32_t)l[j*4+2] | ((uint32_t)l[j*4+3] << 16));
            }
        }
        // B tile: W rows k0..k0+31, cols 0..127 -> sB[n][k]
        {
            int n = lr;
            const float* wp = &W[(size_t)(k0 + lk * 16) * HID_DIM + n];
            unsigned short h[16], l[16];
#pragma unroll
            for (int j = 0; j < 16; j++)
                splitbf(wp[j * HID_DIM], h[j], l[j]);
            int base = n * SROW + lk * 16;
#pragma unroll
            for (int j = 0; j < 4; j++) {
                *(uint2*)&sBh[base + j * 4] = make_uint2(
                    (uint32_t)h[j*4+0] | ((uint32_t)h[j*4+1] << 16),
                    (uint32_t)h[j*4+2] | ((uint32_t)h[j*4+3] << 16));
                *(uint2*)&sBl[base + j * 4] = make_uint2(
                    (uint32_t)l[j*4+0] | ((uint32_t)l[j*4+1] << 16),
                    (uint32_t)l[j*4+2] | ((uint32_t)l[j*4+3] << 16));
            }
        }
        __syncthreads();

#pragma unroll
        for (int kk = 0; kk < 32; kk += 16) {
            uint32_t ah[4][4], al[4][4];
#pragma unroll
            for (int mt = 0; mt < 4; mt++) {
                int row = warp_m + mt * 16 + g;
                int b0 = row * SROW + kk + 2 * t;
                ah[mt][0] = *(const uint32_t*)&sAh[b0];
                ah[mt][1] = *(const uint32_t*)&sAh[b0 + 8 * SROW];
                ah[mt][2] = *(const uint32_t*)&sAh[b0 + 8];
                ah[mt][3] = *(const uint32_t*)&sAh[b0 + 8 * SROW + 8];
                al[mt][0] = *(const uint32_t*)&sAl[b0];
                al[mt][1] = *(const uint32_t*)&sAl[b0 + 8 * SROW];
                al[mt][2] = *(const uint32_t*)&sAl[b0 + 8];
                al[mt][3] = *(const uint32_t*)&sAl[b0 + 8 * SROW + 8];
            }
            uint32_t bh[4][2], bl[4][2];
#pragma unroll
            for (int nt = 0; nt < 4; nt++) {
                int nr = warp_n + nt * 8 + g;
                int b0 = nr * SROW + kk + 2 * t;
                bh[nt][0] = *(const uint32_t*)&sBh[b0];
                bh[nt][1] = *(const uint32_t*)&sBh[b0 + 8];
                bl[nt][0] = *(const uint32_t*)&sBl[b0];
                bl[nt][1] = *(const uint32_t*)&sBl[b0 + 8];
            }
#pragma unroll
            for (int mt = 0; mt < 4; mt++)
#pragma unroll
                for (int nt = 0; nt < 4; nt++) {
                    mma16816(acc[mt][nt], ah[mt], bh[nt]);
                    mma16816(acc[mt][nt], al[mt], bh[nt]);
                    mma16816(acc[mt][nt], ah[mt], bl[nt]);
                }
        }
    }

    // epilogue: fp16 store (half2 per col pair)
#pragma unroll
    for (int mt = 0; mt < 4; mt++) {
        int row = block_row + warp_m + mt * 16 + g;
#pragma unroll
        for (int nt = 0; nt < 4; nt++) {
            int col = warp_n + nt * 8 + 2 * t;
            if (row < M) {
                __half2 hv = __floats2half2_rn(acc[mt][nt][0], acc[mt][nt][1]);
                *(__half2*)&H[(size_t)row * HID_DIM + col] = hv;
            }
            if (row + 8 < M) {
                __half2 hv = __floats2half2_rn(acc[mt][nt][2], acc[mt][nt][3]);
                *(__half2*)&H[(size_t)(row + 8) * HID_DIM + col] = hv;
            }
        }
    }
}

// ---------------------------------------------------------------------------
// GEMM2 via mma.sync bf16 3-split: g2 = hs2[M,128] @ W2[128,64], fp16 out.
// ---------------------------------------------------------------------------
__global__ __launch_bounds__(256)
void gemm2_mma_kernel(const float* __restrict__ A, const float* __restrict__ W,
                      unsigned short* __restrict__ G, int M) {
    __shared__ __align__(16) unsigned short sAh[128 * SROW];
    __shared__ __align__(16) unsigned short sAl[128 * SROW];
    __shared__ __align__(16) unsigned short sBh[64 * SROW];
    __shared__ __align__(16) unsigned short sBl[64 * SROW];

    const int tid = threadIdx.x;
    const int lane = tid & 31, wid = tid >> 5;
    const int g = lane >> 2, t = lane & 3;
    const int warp_m = (wid & 1) * 64;
    const int warp_n = (wid >> 1) * 16;
    const int block_row = blockIdx.x * 128;

    float acc[4][2][4];
#pragma unroll
    for (int i = 0; i < 4; i++)
#pragma unroll
        for (int j = 0; j < 2; j++)
#pragma unroll
            for (int q = 0; q < 4; q++) acc[i][j][q] = 0.0f;

    const int lr = tid >> 1;
    const int lk = tid & 1;
    const int br = tid >> 2;
    const int bq = tid & 3;

    for (int k0 = 0; k0 < HID_DIM; k0 += 32) {
        {
            int grow = block_row + lr;
            float v[16];
            if (grow < M) {
                const float4* ap =
                    (const float4*)&A[(size_t)grow * HID_DIM + k0 + lk * 16];
#pragma unroll
                for (int j = 0; j < 4; j++) {
                    float4 f = ap[j];
                    v[j * 4 + 0] = f.x; v[j * 4 + 1] = f.y;
                    v[j * 4 + 2] = f.z; v[j * 4 + 3] = f.w;
                }
            } else {
#pragma unroll
                for (int j = 0; j < 16; j++) v[j] = 0.0f;
            }
            unsigned short h[16], l[16];
#pragma unroll
            for (int j = 0; j < 16; j++) splitbf(v[j], h[j], l[j]);
            int base = lr * SROW + lk * 16;
#pragma unroll
            for (int j = 0; j < 4; j++) {
                *(uint2*)&sAh[base + j * 4] = make_uint2(
                    (uint32_t)h[j*4+0] | ((uint32_t)h[j*4+1] << 16),
                    (uint32_t)h[j*4+2] | ((uint32_t)h[j*4+3] << 16));
                *(uint2*)&sAl[base + j * 4] = make_uint2(
                    (uint32_t)l[j*4+0] | ((uint32_t)l[j*4+1] << 16),
                    (uint32_t)l[j*4+2] | ((uint32_t)l[j*4+3] << 16));
            }
        }
        {
            const float* wp = &W[(size_t)(k0 + bq * 8) * OUT_DIM + br];
            unsigned short h[8], l[8];
#pragma unroll
            for (int j = 0; j < 8; j++)
                splitbf(wp[j * OUT_DIM], h[j], l[j]);
            int base = br * SROW + bq * 8;
#pragma unroll
            for (int j = 0; j < 2; j++) {
                *(uint2*)&sBh[base + j * 4] = make_uint2(
                    (uint32_t)h[j*4+0] | ((uint32_t)h[j*4+1] << 16),
                    (uint32_t)h[j*4+2] | ((uint32_t)h[j*4+3] << 16));
                *(uint2*)&sBl[base + j * 4] = make_uint2(
                    (uint32_t)l[j*4+0] | ((uint32_t)l[j*4+1] << 16),
                    (uint32_t)l[j*4+2] | ((uint32_t)l[j*4+3] << 16));
            }
        }
        __syncthreads();

#pragma unroll
        for (int kk = 0; kk < 32; kk += 16) {
            uint32_t ah[4][4], al[4][4];
#pragma unroll
            for (int mt = 0; mt < 4; mt++) {
                int row = warp_m + mt * 16 + g;
                int b0 = row * SROW + kk + 2 * t;
                ah[mt][0] = *(const uint32_t*)&sAh[b0];
                ah[mt][1] = *(const uint32_t*)&sAh[b0 + 8 * SROW];
                ah[mt][2] = *(const uint32_t*)&sAh[b0 + 8];
                ah[mt][3] = *(const uint32_t*)&sAh[b0 + 8 * SROW + 8];
                al[mt][0] = *(const uint32_t*)&sAl[b0];
                al[mt][1] = *(const uint32_t*)&sAl[b0 + 8 * SROW];
                al[mt][2] = *(const uint32_t*)&sAl[b0 + 8];
                al[mt][3] = *(const uint32_t*)&sAl[b0 + 8 * SROW + 8];
            }
            uint32_t bh[2][2], bl[2][2];
#pragma unroll
            for (int nt = 0; nt < 2; nt++) {
                int nr = warp_n + nt * 8 + g;
                int b0 = nr * SROW + kk + 2 * t;
                bh[nt][0] = *(const uint32_t*)&sBh[b0];
                bh[nt][1] = *(const uint32_t*)&sBh[b0 + 8];
                bl[nt][0] = *(const uint32_t*)&sBl[b0];
                bl[nt][1] = *(const uint32_t*)&sBl[b0 + 8];
            }
#pragma unroll
            for (int mt = 0; mt < 4; mt++)
#pragma unroll
                for (int nt = 0; nt < 2; nt++) {
                    mma16816(acc[mt][nt], ah[mt], bh[nt]);
                    mma16816(acc[mt][nt], al[mt], bh[nt]);
                    mma16816(acc[mt][nt], ah[mt], bl[nt]);
                }
        }
        __syncthreads();
    }

    // epilogue: fp16 store
#pragma unroll
    for (int mt = 0; mt < 4; mt++) {
        int row = block_row + warp_m + mt * 16 + g;
#pragma unroll
        for (int nt = 0; nt < 2; nt++) {
            int col = warp_n + nt * 8 + 2 * t;
            if (row < M) {
                __half2 hv = __floats2half2_rn(acc[mt][nt][0], acc[mt][nt][1]);
                *(__half2*)&G[(size_t)row * OUT_DIM + col] = hv;
            }
            if (row + 8 < M) {
                __half2 hv = __floats2half2_rn(acc[mt][nt][2], acc[mt][nt][3]);
                *(__half2*)&G[(size_t)(row + 8) * OUT_DIM + col] = hv;
            }
        }
    }
}

// ---------------------------------------------------------------------------
// Layer-1 aggregation: warp per node; gathers fp16 h1 (8B/lane/edge).
// hs2[i] = relu((sum_j h1[u_j]*ns[u_j]) * nd[i] + b1) * ns[i]   (fp32 accum)
// ---------------------------------------------------------------------------
__global__ __launch_bounds__(256)
void agg1_kernel(const float* __restrict__ b1, int n) {
    int node = blockIdx.x * (blockDim.x >> 5) + (threadIdx.x >> 5);
    if (node >= n) return;
    int lane = threadIdx.x & 31;
    int s = g_row_ptr[node], e = g_row_ptr[node + 1];
    float4 acc = make_float4(0.f, 0.f, 0.f, 0.f);
#pragma unroll 8
    for (int j = s; j < e; j++) {
        int u = g_csr_src[j];
        float nsu = __ldg(&g_ns[u]);
        uint2 p = *(const uint2*)&g_h1h[(size_t)u * HID_DIM + lane * 4];
        float2 f01 = __half22float2(*reinterpret_cast<__half2*>(&p.x));
        float2 f23 = __half22float2(*reinterpret_cast<__half2*>(&p.y));
        acc.x = fmaf(f01.x, nsu, acc.x);
        acc.y = fmaf(f01.y, nsu, acc.y);
        acc.z = fmaf(f23.x, nsu, acc.z);
        acc.w = fmaf(f23.y, nsu, acc.w);
    }
    float nd = g_nd[node], ns = g_ns[node];
    float4 bb = *(const float4*)&b1[lane * 4];
    float4 o;
    o.x = fmaxf(fmaf(acc.x, nd, bb.x), 0.f) * ns;
    o.y = fmaxf(fmaf(acc.y, nd, bb.y), 0.f) * ns;
    o.z = fmaxf(fmaf(acc.z, nd, bb.z), 0.f) * ns;
    o.w = fmaxf(fmaf(acc.w, nd, bb.w), 0.f) * ns;
    *(float4*)&g_hs2[(size_t)node * HID_DIM + lane * 4] = o;
}

// ---------------------------------------------------------------------------
// Layer-2 aggregation: gathers fp16 g2 (4B/lane/edge), fp32 accum/output.
// ---------------------------------------------------------------------------
__global__ __launch_bounds__(256)
void agg2_kernel(const float* __restrict__ b2, float* __restrict__ out, int n) {
    int node = blockIdx.x * (blockDim.x >> 5) + (threadIdx.x >> 5);
    if (node >= n) return;
    int lane = threadIdx.x & 31;
    int s = g_row_ptr[node], e = g_row_ptr[node + 1];
    float2 acc = make_float2(0.f, 0.f);
#pragma unroll 8
    for (int j = s; j < e; j++) {
        int u = g_csr_src[j];
        uint32_t p = *(const uint32_t*)&g_g2h[(size_t)u * OUT_DIM + lane * 2];
        float2 f = __half22float2(*reinterpret_cast<__half2*>(&p));
        acc.x += f.x; acc.y += f.y;
    }
    float nd = g_nd[node];
    float2 bb = *(const float2*)&b2[lane * 2];
    float2 o;
    o.x = fmaf(acc.x, nd, bb.x);
    o.y = fmaf(acc.y, nd, bb.y);
    *(float2*)&out[(size_t)node * OUT_DIM + lane * 2] = o;
}

// ---------------------------------------------------------------------------
extern "C" void kernel_launch(void* const* d_in, const int* in_sizes, int n_in,
                              void* d_out, int out_size) {
    const float* x   = (const float*)d_in[0];
    const float* W1  = (const float*)d_in[1];
    const float* b1  = (const float*)d_in[2];
    const float* W2  = (const float*)d_in[3];
    const float* b2  = (const float*)d_in[4];
    const int*   src = (const int*)d_in[5];
    const int*   dst = (const int*)d_in[6];
    float* out = (float*)d_out;

    const int n = in_sizes[0] / IN_DIM;      // 50000
    const int E = in_sizes[5];               // 800000

    unsigned short *p_h1h, *p_g2h;
    float *p_hs2;
    cudaGetSymbolAddress((void**)&p_h1h, g_h1h);
    cudaGetSymbolAddress((void**)&p_hs2, g_hs2);
    cudaGetSymbolAddress((void**)&p_g2h, g_g2h);

    const int nscan = (n + SCAN_BLK - 1) / SCAN_BLK;
    const int GEMM1_SMEM = 8 * TILE_ELEMS * (int)sizeof(unsigned short); // 73728
    cudaFuncSetAttribute(gemm1_mma_kernel,
                         cudaFuncAttributeMaxDynamicSharedMemorySize,
                         GEMM1_SMEM);

    // fork: GEMM1 (depends only on x, W1) concurrent with structure chain.
    cudaStream_t s2;
    cudaStreamCreate(&s2);
    cudaEvent_t e_fork, e_join;
    cudaEventCreateWithFlags(&e_fork, cudaEventDisableTiming);
    cudaEventCreateWithFlags(&e_join, cudaEventDisableTiming);

    cudaEventRecord(e_fork, 0);
    cudaStreamWaitEvent(s2, e_fork, 0);

    gemm1_mma_kernel<<<(n + 127) / 128, 256, GEMM1_SMEM, s2>>>(x, W1, p_h1h, n);
    cudaEventRecord(e_join, s2);

    zero_kernel<<<(n + 255) / 256, 256>>>(n);
    deg_kernel<<<(E + 255) / 256, 256>>>(src, dst, E);
    scan1_kernel<<<nscan, SCAN_BLK>>>(n);
    scan3_kernel<<<nscan, SCAN_BLK>>>(n);
    csr_fill_kernel<<<(E + 255) / 256, 256>>>(src, dst, E);

    cudaStreamWaitEvent(0, e_join, 0);
    agg1_kernel<<<(n + 7) / 8, 256>>>(b1, n);
    gemm2_mma_kernel<<<(n + 127) / 128, 256>>>(p_hs2, W2, p_g2h, n);
    agg2_kernel<<<(n + 7) / 8, 256>>>(b2, out, n);
}